// round 9
// baseline (speedup 1.0000x reference)
#include <cuda_runtime.h>
#include <math.h>

#define BB 2
#define LL 2048
#define HID 4096
#define NH 32
#define HD 128
#define MM (BB*LL)           // 4096 tokens
#define QKVN (3*HID)         // 12288
#define BH (BB*NH)           // 64
#define SCALE 0.08838834764831845f   // 1/sqrt(128)
#define C2E 0.1275313945069287f      // SCALE * log2(e)
#define PADM 4224
#define MBLK 33

// -------- scratch (static device globals; allocation-free) --------
__device__ float g_q[(size_t)BH*LL*HD];
__device__ float g_k[(size_t)BH*LL*HD];
__device__ float g_v[(size_t)BH*LL*HD];
__device__ float g_ctx[(size_t)PADM*HID];
__device__ int   g_vm[MM];
__device__ int   g_perm[PADM];
__device__ int   g_iperm[MM];
__device__ int   g_NvPad;
__device__ float g_cos[LL*HD];
__device__ float g_sin[LL*HD];

// -------- prep --------
__global__ void prep_kernel(const int* __restrict__ tt) {
    int idx = blockIdx.x * blockDim.x + threadIdx.x;
    if (idx < MM) {
        int l = idx & (LL - 1);
        g_vm[idx] = (l < LL - 1) && (tt[idx] == 1) && (tt[idx + 1] == 1);
    }
    if (idx < LL * HD) {
        int p = idx / HD;
        int d = idx & (HD - 1);
        int j = d & 63;
        double inv = exp(-log(10000.0) * (double)(2 * j) / 128.0);
        double ang = (double)p * inv;
        g_cos[idx] = (float)cos(ang);
        g_sin[idx] = (float)sin(ang);
    }
}

// -------- deterministic partition scan --------
__global__ void scan_kernel() {
    __shared__ int s[1024];
    int t = threadIdx.x;
    int flags[4];
    int c = 0;
#pragma unroll
    for (int i = 0; i < 4; i++) { flags[i] = g_vm[t * 4 + i]; c += flags[i]; }
    s[t] = c;
    __syncthreads();
    for (int off = 1; off < 1024; off <<= 1) {
        int v = s[t];
        int add = (t >= off) ? s[t - off] : 0;
        __syncthreads();
        s[t] = v + add;
        __syncthreads();
    }
    int Nv = s[1023];
    int ex = s[t] - c;
    int nvpad = (Nv + 127) & ~127;
    for (int i = t; i < PADM; i += 1024) g_perm[i] = -1;
    __syncthreads();
    int vrun = ex;
#pragma unroll
    for (int i = 0; i < 4; i++) {
        int g = t * 4 + i;
        int dst;
        if (flags[i]) { dst = vrun; vrun++; }
        else          { dst = nvpad + (g - vrun); }
        g_perm[dst] = g;
        g_iperm[g] = dst;
    }
    if (t == 0) g_NvPad = nvpad;
}

// -------- TF32 helpers --------
__device__ __forceinline__ unsigned f2tf32(float f) {
    unsigned o;
    asm("cvt.rna.tf32.f32 %0, %1;" : "=r"(o) : "f"(f));
    return o;
}
__device__ __forceinline__ float fexp2(float x) {
    float y;
    asm("ex2.approx.ftz.f32 %0, %1;" : "=f"(y) : "f"(x));
    return y;
}
__device__ __forceinline__ void mma_tf32(float* d, const unsigned* a, const unsigned* b) {
    asm volatile(
        "mma.sync.aligned.m16n8k8.row.col.f32.tf32.tf32.f32 "
        "{%0,%1,%2,%3},{%4,%5,%6,%7},{%8,%9},{%0,%1,%2,%3};\n"
        : "+f"(d[0]), "+f"(d[1]), "+f"(d[2]), "+f"(d[3])
        : "r"(a[0]), "r"(a[1]), "r"(a[2]), "r"(a[3]), "r"(b[0]), "r"(b[1]));
}

#define KS 36

// -------- routed QKV GEMM (TF32 MMA) --------
__global__ __launch_bounds__(256) void qkv_mma(const float* __restrict__ A,
                                               const float* __restrict__ Wv,
                                               const float* __restrict__ Wl) {
    __shared__ unsigned As[128][KS];
    __shared__ unsigned Bs[128][KS];
    const int m0 = blockIdx.x * 128;
    const int n0 = blockIdx.y * 128;
    const int t = threadIdx.x;
    const int lane = t & 31, w = t >> 5;
    const int wm = (w & 1) * 64, wn = (w >> 1) * 32;
    const int lr = t >> 1;
    const int lk = (t & 1) * 16;
    const int qr = lane >> 2, qc = lane & 3;

    const float* W = (m0 < g_NvPad) ? Wv : Wl;
    int tokA = g_perm[m0 + lr];
    const float* Arow = A + (size_t)(tokA < 0 ? 0 : tokA) * HID + lk;
    const float* Brow = W + (size_t)(n0 + lr) * HID + lk;

    float acc[4][4][4] = {};
    for (int k0 = 0; k0 < HID; k0 += 32) {
        float4 av[4], bv[4];
#pragma unroll
        for (int i = 0; i < 4; i++) {
            av[i] = *(const float4*)(Arow + k0 + 4 * i);
            bv[i] = *(const float4*)(Brow + k0 + 4 * i);
        }
        __syncthreads();
#pragma unroll
        for (int i = 0; i < 4; i++) {
            *(uint4*)&As[lr][lk + 4 * i] = make_uint4(f2tf32(av[i].x), f2tf32(av[i].y), f2tf32(av[i].z), f2tf32(av[i].w));
            *(uint4*)&Bs[lr][lk + 4 * i] = make_uint4(f2tf32(bv[i].x), f2tf32(bv[i].y), f2tf32(bv[i].z), f2tf32(bv[i].w));
        }
        __syncthreads();
#pragma unroll
        for (int kc = 0; kc < 32; kc += 8) {
            unsigned bf[4][2];
#pragma unroll
            for (int nt = 0; nt < 4; nt++) {
                bf[nt][0] = Bs[wn + nt * 8 + qr][kc + qc];
                bf[nt][1] = Bs[wn + nt * 8 + qr][kc + qc + 4];
            }
#pragma unroll
            for (int mt = 0; mt < 4; mt++) {
                unsigned af[4];
                af[0] = As[wm + mt * 16 + qr][kc + qc];
                af[1] = As[wm + mt * 16 + qr + 8][kc + qc];
                af[2] = As[wm + mt * 16 + qr][kc + qc + 4];
                af[3] = As[wm + mt * 16 + qr + 8][kc + qc + 4];
#pragma unroll
                for (int nt = 0; nt < 4; nt++)
                    mma_tf32(acc[mt][nt], af, bf[nt]);
            }
        }
    }
#pragma unroll
    for (int mt = 0; mt < 4; mt++) {
        int r0 = m0 + wm + mt * 16 + qr;
        int tok0 = g_perm[r0], tok1 = g_perm[r0 + 8];
#pragma unroll
        for (int nt = 0; nt < 4; nt++) {
            int cb = n0 + wn + nt * 8 + qc * 2;
            int part = cb >> 12, rem = cb & 4095, head = rem >> 7, dd = rem & 127;
            float* base = (part == 0) ? g_q : (part == 1) ? g_k : g_v;
            if (tok0 >= 0) {
                int b = tok0 >> 11, l = tok0 & 2047;
                *(float2*)&base[((size_t)(b * NH + head) * LL + l) * HD + dd] =
                    make_float2(acc[mt][nt][0], acc[mt][nt][1]);
            }
            if (tok1 >= 0) {
                int b = tok1 >> 11, l = tok1 & 2047;
                *(float2*)&base[((size_t)(b * NH + head) * LL + l) * HD + dd] =
                    make_float2(acc[mt][nt][2], acc[mt][nt][3]);
            }
        }
    }
}

// -------- routed dense GEMM (TF32 MMA) --------
__global__ __launch_bounds__(256) void dense_mma(float* __restrict__ out,
                                                 const float* __restrict__ Wv,
                                                 const float* __restrict__ Wl) {
    __shared__ unsigned As[128][KS];
    __shared__ unsigned Bs[128][KS];
    const int m0 = blockIdx.x * 128;
    const int n0 = blockIdx.y * 128;
    const int t = threadIdx.x;
    const int lane = t & 31, w = t >> 5;
    const int wm = (w & 1) * 64, wn = (w >> 1) * 32;
    const int lr = t >> 1;
    const int lk = (t & 1) * 16;
    const int qr = lane >> 2, qc = lane & 3;

    const float* W = (m0 < g_NvPad) ? Wv : Wl;
    const float* Arow = g_ctx + (size_t)(m0 + lr) * HID + lk;
    const float* Brow = W + (size_t)(n0 + lr) * HID + lk;

    float acc[4][4][4] = {};
    for (int k0 = 0; k0 < HID; k0 += 32) {
        float4 av[4], bv[4];
#pragma unroll
        for (int i = 0; i < 4; i++) {
            av[i] = *(const float4*)(Arow + k0 + 4 * i);
            bv[i] = *(const float4*)(Brow + k0 + 4 * i);
        }
        __syncthreads();
#pragma unroll
        for (int i = 0; i < 4; i++) {
            *(uint4*)&As[lr][lk + 4 * i] = make_uint4(f2tf32(av[i].x), f2tf32(av[i].y), f2tf32(av[i].z), f2tf32(av[i].w));
            *(uint4*)&Bs[lr][lk + 4 * i] = make_uint4(f2tf32(bv[i].x), f2tf32(bv[i].y), f2tf32(bv[i].z), f2tf32(bv[i].w));
        }
        __syncthreads();
#pragma unroll
        for (int kc = 0; kc < 32; kc += 8) {
            unsigned bf[4][2];
#pragma unroll
            for (int nt = 0; nt < 4; nt++) {
                bf[nt][0] = Bs[wn + nt * 8 + qr][kc + qc];
                bf[nt][1] = Bs[wn + nt * 8 + qr][kc + qc + 4];
            }
#pragma unroll
            for (int mt = 0; mt < 4; mt++) {
                unsigned af[4];
                af[0] = As[wm + mt * 16 + qr][kc + qc];
                af[1] = As[wm + mt * 16 + qr + 8][kc + qc];
                af[2] = As[wm + mt * 16 + qr][kc + qc + 4];
                af[3] = As[wm + mt * 16 + qr + 8][kc + qc + 4];
#pragma unroll
                for (int nt = 0; nt < 4; nt++)
                    mma_tf32(acc[mt][nt], af, bf[nt]);
            }
        }
    }
#pragma unroll
    for (int mt = 0; mt < 4; mt++) {
        int r0 = m0 + wm + mt * 16 + qr;
        int tok0 = g_perm[r0], tok1 = g_perm[r0 + 8];
#pragma unroll
        for (int nt = 0; nt < 4; nt++) {
            int cb = n0 + wn + nt * 8 + qc * 2;
            if (tok0 >= 0)
                *(float2*)&out[(size_t)tok0 * HID + cb] = make_float2(acc[mt][nt][0], acc[mt][nt][1]);
            if (tok1 >= 0)
                *(float2*)&out[(size_t)tok1 * HID + cb] = make_float2(acc[mt][nt][2], acc[mt][nt][3]);
        }
    }
}

// -------- RoPE in-place --------
__global__ void rope_kernel(const int* __restrict__ pos_ids) {
    int blk = blockIdx.x;
    int l  = blk & (LL - 1);
    int bh = blk >> 11;
    int b  = bh >> 5;
    int d  = threadIdx.x;
    int p  = pos_ids[b * LL + l];
    if (p < 0) p = 0;
    if (p >= LL) p = LL - 1;
    size_t base = ((size_t)bh * LL + l) * HD;
    float c = g_cos[p * HD + d];
    float s = g_sin[p * HD + d];
    int pd = (d < 64) ? d + 64 : d - 64;
    float q0 = g_q[base + d], qp = g_q[base + pd];
    float k0 = g_k[base + d], kp = g_k[base + pd];
    float qr = (d < 64) ? -qp : qp;
    float kr = (d < 64) ? -kp : kp;
    __syncthreads();
    g_q[base + d] = q0 * c + qr * s;
    g_k[base + d] = k0 * c + kr * s;
}

// -------- flash attention v2: TF32 MMA, 4 warps, q-tile 64, swizzled smem --------
// smem: Qs 64x128, Ks 64x128, Vt 128x64, Ps 64x64  -> 28672 words = 112 KB -> 2 CTA/SM
#define SM2_QS 0
#define SM2_KS (64*128)
#define SM2_VT (2*64*128)
#define SM2_PS (3*64*128)
#define SM2_TOT (3*64*128 + 64*64)     // 28672 words

__device__ __forceinline__ int swq(int row, int col) {      // stride-128 arrays
    return row * 128 + (col ^ ((row & 7) << 2));
}
__device__ __forceinline__ int swv(int row, int col) {      // stride-64 arrays
    return row * 64 + (col ^ ((row & 7) << 2));
}

__global__ __launch_bounds__(128, 2) void flash_mma2() {
    extern __shared__ unsigned smu[];
    unsigned* Qs = smu + SM2_QS;
    unsigned* Ks = smu + SM2_KS;
    unsigned* Vt = smu + SM2_VT;
    unsigned* Ps = smu + SM2_PS;

    const int bh = blockIdx.y;
    const int m0 = blockIdx.x * 64;
    const float* Q = g_q + (size_t)bh * LL * HD;
    const float* K = g_k + (size_t)bh * LL * HD;
    const float* V = g_v + (size_t)bh * LL * HD;

    const int t = threadIdx.x;
    const int lane = t & 31, w = t >> 5;    // 4 warps
    const int wm = w * 16;
    const int qr = lane >> 2, qc = lane & 3;

    const int lrow = t >> 1;                // load row 0..63
    const int lhalf = (t & 1) * 64;         // column half

    // --- load + convert Q tile (64x128, swizzled) ---
#pragma unroll
    for (int i = 0; i < 16; i++) {
        int col = lhalf + 4 * i;
        float4 q4 = *(const float4*)&Q[(size_t)(m0 + lrow) * HD + col];
        *(uint4*)&Qs[swq(lrow, col)] =
            make_uint4(f2tf32(q4.x), f2tf32(q4.y), f2tf32(q4.z), f2tf32(q4.w));
    }

    float o[16][4];
#pragma unroll
    for (int nt = 0; nt < 16; nt++)
#pragma unroll
        for (int j = 0; j < 4; j++) o[nt][j] = 0.f;
    float mrow0 = -1e30f, mrow1 = -1e30f, srow0 = 0.f, srow1 = 0.f;

    for (int j0 = 0; j0 < LL; j0 += 64) {
        __syncthreads();   // prior iteration's reads of Ks/Vt done (also orders Qs fill)
        // --- load + convert K (row-major swizzled) and V (transposed swizzled) ---
#pragma unroll
        for (int i = 0; i < 16; i++) {
            int col = lhalf + 4 * i;
            float4 k4 = *(const float4*)&K[(size_t)(j0 + lrow) * HD + col];
            *(uint4*)&Ks[swq(lrow, col)] =
                make_uint4(f2tf32(k4.x), f2tf32(k4.y), f2tf32(k4.z), f2tf32(k4.w));
            float4 v4 = *(const float4*)&V[(size_t)(j0 + lrow) * HD + col];
            Vt[swv(col + 0, lrow)] = f2tf32(v4.x);
            Vt[swv(col + 1, lrow)] = f2tf32(v4.y);
            Vt[swv(col + 2, lrow)] = f2tf32(v4.z);
            Vt[swv(col + 3, lrow)] = f2tf32(v4.w);
        }
        __syncthreads();

        // --- S = Q K^T : warp computes 16 rows x 64 cols ---
        float accs[8][4];
#pragma unroll
        for (int nt = 0; nt < 8; nt++)
#pragma unroll
            for (int j = 0; j < 4; j++) accs[nt][j] = 0.f;
#pragma unroll
        for (int kc = 0; kc < 128; kc += 8) {
            unsigned af[4];
            af[0] = Qs[swq(wm + qr,     kc + qc)];
            af[1] = Qs[swq(wm + qr + 8, kc + qc)];
            af[2] = Qs[swq(wm + qr,     kc + qc + 4)];
            af[3] = Qs[swq(wm + qr + 8, kc + qc + 4)];
#pragma unroll
            for (int nt = 0; nt < 8; nt++) {
                unsigned bf[2];
                bf[0] = Ks[swq(nt * 8 + qr, kc + qc)];
                bf[1] = Ks[swq(nt * 8 + qr, kc + qc + 4)];
                mma_tf32(accs[nt], af, bf);
            }
        }

        // --- online softmax (warp-local, rows qr and qr+8) ---
        float tm0 = -1e30f, tm1 = -1e30f;
#pragma unroll
        for (int nt = 0; nt < 8; nt++) {
            tm0 = fmaxf(tm0, fmaxf(accs[nt][0], accs[nt][1]));
            tm1 = fmaxf(tm1, fmaxf(accs[nt][2], accs[nt][3]));
        }
        tm0 *= C2E; tm1 *= C2E;
#pragma unroll
        for (int ms = 1; ms < 4; ms <<= 1) {
            tm0 = fmaxf(tm0, __shfl_xor_sync(0xffffffffu, tm0, ms));
            tm1 = fmaxf(tm1, __shfl_xor_sync(0xffffffffu, tm1, ms));
        }
        float mn0 = fmaxf(mrow0, tm0), mn1 = fmaxf(mrow1, tm1);
        float fac0 = fexp2(mrow0 - mn0), fac1 = fexp2(mrow1 - mn1);
        mrow0 = mn0; mrow1 = mn1;
        float sum0 = 0.f, sum1 = 0.f;
#pragma unroll
        for (int nt = 0; nt < 8; nt++) {
            float p0 = fexp2(accs[nt][0] * C2E - mn0);
            float p1 = fexp2(accs[nt][1] * C2E - mn0);
            float p2 = fexp2(accs[nt][2] * C2E - mn1);
            float p3 = fexp2(accs[nt][3] * C2E - mn1);
            sum0 += p0 + p1; sum1 += p2 + p3;
            *(uint2*)&Ps[swv(wm + qr,     nt * 8 + 2 * qc)] =
                make_uint2(f2tf32(p0), f2tf32(p1));
            *(uint2*)&Ps[swv(wm + qr + 8, nt * 8 + 2 * qc)] =
                make_uint2(f2tf32(p2), f2tf32(p3));
        }
#pragma unroll
        for (int ms = 1; ms < 4; ms <<= 1) {
            sum0 += __shfl_xor_sync(0xffffffffu, sum0, ms);
            sum1 += __shfl_xor_sync(0xffffffffu, sum1, ms);
        }
        srow0 = srow0 * fac0 + sum0;
        srow1 = srow1 * fac1 + sum1;
#pragma unroll
        for (int nt = 0; nt < 16; nt++) {
            o[nt][0] *= fac0; o[nt][1] *= fac0;
            o[nt][2] *= fac1; o[nt][3] *= fac1;
        }

        // --- O += P V : Ps is warp-private (same warp writes & reads) ---
#pragma unroll
        for (int kc = 0; kc < 64; kc += 8) {
            unsigned af[4];
            af[0] = Ps[swv(wm + qr,     kc + qc)];
            af[1] = Ps[swv(wm + qr + 8, kc + qc)];
            af[2] = Ps[swv(wm + qr,     kc + qc + 4)];
            af[3] = Ps[swv(wm + qr + 8, kc + qc + 4)];
#pragma unroll
            for (int nt = 0; nt < 16; nt++) {
                unsigned bf[2];
                bf[0] = Vt[swv(nt * 8 + qr, kc + qc)];
                bf[1] = Vt[swv(nt * 8 + qr, kc + qc + 4)];
                mma_tf32(o[nt], af, bf);
            }
        }
    }

    // --- epilogue: normalize, write ctx at permuted rows ---
    const int b = bh >> 5;
    const int h = bh & 31;
    float inv0 = 1.0f / srow0, inv1 = 1.0f / srow1;
    int prow0 = g_iperm[b * LL + m0 + wm + qr];
    int prow1 = g_iperm[b * LL + m0 + wm + qr + 8];
    size_t base0 = (size_t)prow0 * HID + h * HD;
    size_t base1 = (size_t)prow1 * HID + h * HD;
#pragma unroll
    for (int nt = 0; nt < 16; nt++) {
        int cb = nt * 8 + 2 * qc;
        *(float2*)&g_ctx[base0 + cb] = make_float2(o[nt][0] * inv0, o[nt][1] * inv0);
        *(float2*)&g_ctx[base1 + cb] = make_float2(o[nt][2] * inv1, o[nt][3] * inv1);
    }
}

extern "C" void kernel_launch(void* const* d_in, const int* in_sizes, int n_in,
                              void* d_out, int out_size) {
    const float* hs   = (const float*)d_in[0];
    const int*   tt   = (const int*)d_in[1];
    const int*   pos  = (const int*)d_in[2];
    // d_in[3] = attention_mask (all zeros; reference math ignores it)
    const float* wvq  = (const float*)d_in[4];
    const float* wlq  = (const float*)d_in[5];
    const float* wvd  = (const float*)d_in[6];
    const float* wld  = (const float*)d_in[7];
    float* out = (float*)d_out;

    cudaFuncSetAttribute(flash_mma2, cudaFuncAttributeMaxDynamicSharedMemorySize,
                         SM2_TOT * (int)sizeof(unsigned));

    prep_kernel<<<1024, 256>>>(tt);
    scan_kernel<<<1, 1024>>>();
    qkv_mma<<<dim3(MBLK, QKVN / 128), 256>>>(hs, wvq, wlq);
    rope_kernel<<<BH * LL, 128>>>(pos);
    flash_mma2<<<dim3(LL / 64, BH), 128, SM2_TOT * (int)sizeof(unsigned)>>>();
    dense_mma<<<dim3(MBLK, HID / 128), 256>>>(out, wvd, wld);
}